// round 11
// baseline (speedup 1.0000x reference)
#include <cuda_runtime.h>

// Bilinear resample: B=16, S=128, C=128, fp32.
// R11: R10 byte-identical body (one-wave grid-stride band schedule +
// pipelined offsets load) with ONE isolated change: output stores use
// __stcs (evict-first). The 128MB write stream is never re-read; keeping
// it from write-allocating in L2 protects the gather band's L2 residency
// (R7 tested .cs confounded with a register/occupancy loss — this isolates it).

#define S 128
#define C 128
#define C4 (C / 4)                 // float4s per pixel
#define NPIX (16 * S * S)          // 262144
#define NPAIR (NPIX / 2)           // 131072
#define WARPS_PER_CTA 8            // 256 threads
#define NBLOCKS 1184               // one full wave at 8 CTAs/SM
#define NWARPS (NBLOCKS * WARPS_PER_CTA)   // 9472

__device__ __forceinline__ float4 lerp4(float4 v00, float4 v01, float4 v10,
                                        float4 v11, float fx, float fy)
{
    float4 t, bo, o;
    t.x  = v00.x + (v01.x - v00.x) * fx;
    t.y  = v00.y + (v01.y - v00.y) * fx;
    t.z  = v00.z + (v01.z - v00.z) * fx;
    t.w  = v00.w + (v01.w - v00.w) * fx;
    bo.x = v10.x + (v11.x - v10.x) * fx;
    bo.y = v10.y + (v11.y - v10.y) * fx;
    bo.z = v10.z + (v11.z - v10.z) * fx;
    bo.w = v10.w + (v11.w - v10.w) * fx;
    o.x  = t.x + (bo.x - t.x) * fy;
    o.y  = t.y + (bo.y - t.y) * fy;
    o.z  = t.z + (bo.z - t.z) * fy;
    o.w  = t.w + (bo.w - t.w) * fy;
    return o;
}

__global__ __launch_bounds__(256, 7) void resample_kernel(
    const float* __restrict__ offsets,
    const float* __restrict__ inputs,
    float* __restrict__ out)
{
    const int lane = threadIdx.x & 31;
    const int gw = blockIdx.x * WARPS_PER_CTA + (threadIdx.x >> 5);

    const float4* off4 = reinterpret_cast<const float4*>(offsets);
    const float4* in4  = reinterpret_cast<const float4*>(inputs);
    float4*       out4 = reinterpret_cast<float4*>(out);

    // Prologue: load first iteration's offsets.
    float4 off_next = (gw < NPAIR) ? __ldg(off4 + gw)
                                   : make_float4(0.f, 0.f, 0.f, 0.f);

#pragma unroll 1
    for (int p = gw; p < NPAIR; p += NWARPS) {
        const float4 off2 = off_next;
        // Issue next iteration's offsets load NOW; it completes while this
        // iteration's gathers are in flight.
        const int pn = p + NWARPS;
        if (pn < NPAIR) off_next = __ldg(off4 + pn);

        const int pix0 = p * 2;
        const int jA = pix0 & (S - 1);
        const int i  = (pix0 >> 7) & (S - 1);
        const int b  = pix0 >> 14;
        const float4* base = in4 + (size_t)b * (S * S * C4);
        const float fi = (float)i;

        // Reference semantics: clip [0, S-1], rb = ceil.
        const float yA = fminf(fmaxf(off2.x + fi,              0.0f), (float)(S - 1));
        const float xA = fminf(fmaxf(off2.y + (float)jA,       0.0f), (float)(S - 1));
        const float yB = fminf(fmaxf(off2.z + fi,              0.0f), (float)(S - 1));
        const float xB = fminf(fmaxf(off2.w + (float)(jA + 1), 0.0f), (float)(S - 1));

        const float ay0f = floorf(yA), ax0f = floorf(xA);
        const float by0f = floorf(yB), bx0f = floorf(xB);
        const int aY0 = (int)ay0f,      aX0 = (int)ax0f;
        const int aY1 = (int)ceilf(yA), aX1 = (int)ceilf(xA);
        const int bY0 = (int)by0f,      bX0 = (int)bx0f;
        const int bY1 = (int)ceilf(yB), bX1 = (int)ceilf(xB);
        const float afy = yA - ay0f, afx = xA - ax0f;
        const float bfy = yB - by0f, bfx = xB - bx0f;

        // 8 independent coalesced 512B gathers.
        const float4 a00 = __ldg(base + (aY0 * S + aX0) * C4 + lane);
        const float4 a01 = __ldg(base + (aY0 * S + aX1) * C4 + lane);
        const float4 a10 = __ldg(base + (aY1 * S + aX0) * C4 + lane);
        const float4 a11 = __ldg(base + (aY1 * S + aX1) * C4 + lane);
        const float4 b00 = __ldg(base + (bY0 * S + bX0) * C4 + lane);
        const float4 b01 = __ldg(base + (bY0 * S + bX1) * C4 + lane);
        const float4 b10 = __ldg(base + (bY1 * S + bX0) * C4 + lane);
        const float4 b11 = __ldg(base + (bY1 * S + bX1) * C4 + lane);

        float4* outp = out4 + (size_t)pix0 * C4 + lane;
        __stcs(outp,      lerp4(a00, a01, a10, a11, afx, afy));
        __stcs(outp + C4, lerp4(b00, b01, b10, b11, bfx, bfy));
    }
}

extern "C" void kernel_launch(void* const* d_in, const int* in_sizes, int n_in,
                              void* d_out, int out_size)
{
    const float* offsets = (const float*)d_in[0];
    const float* inputs  = (const float*)d_in[1];
    float* out = (float*)d_out;

    resample_kernel<<<NBLOCKS, WARPS_PER_CTA * 32>>>(offsets, inputs, out);
}